// round 12
// baseline (speedup 1.0000x reference)
#include <cuda_runtime.h>
#include <cstdint>

// Persistent STPN: 8-CTA clusters = sync groups. h exchanged via DSMEM
// (st.shared::cluster) + slot mbarriers; consumed via local LDS. No global
// flag traffic, no __syncthreads in the loop. Compute body = R8 (proven),
// weights via LDS.128.

#define NCTA 128
#define NTHR 512
#define CLSZ 8

namespace {
constexpr int kB = 32;
constexpr int kS = 64;
constexpr int kI = 256;
constexpr int kH = 256;
constexpr int kO = 128;
constexpr int kF = 512;
constexpr int kRows = 32;
}

typedef unsigned long long u64;

__device__ __forceinline__ uint32_t smem_u32(const void* p) {
  uint32_t a;
  asm("{ .reg .u64 t; cvta.to.shared.u64 t, %1; cvt.u32.u64 %0, t; }"
      : "=r"(a) : "l"(p));
  return a;
}
__device__ __forceinline__ uint32_t mapa_u32(uint32_t addr, uint32_t rank) {
  uint32_t r;
  asm("mapa.shared::cluster.u32 %0, %1, %2;" : "=r"(r) : "r"(addr), "r"(rank));
  return r;
}
__device__ __forceinline__ void st_cluster_u64(uint32_t addr, u64 v) {
  asm volatile("st.shared::cluster.u64 [%0], %1;" :: "r"(addr), "l"(v) : "memory");
}
__device__ __forceinline__ void mbar_init(uint32_t addr, unsigned cnt) {
  asm volatile("mbarrier.init.shared.b64 [%0], %1;" :: "r"(addr), "r"(cnt) : "memory");
}
__device__ __forceinline__ void mbar_arrive_cluster(uint32_t addr) {
  asm volatile("mbarrier.arrive.release.cluster.shared::cluster.b64 _, [%0];"
               :: "r"(addr) : "memory");
}
__device__ __forceinline__ void mbar_wait(uint32_t addr, unsigned parity) {
  asm volatile(
      "{\n\t.reg .pred P;\n\t"
      "W_%=:\n\t"
      "mbarrier.try_wait.parity.acquire.cluster.shared::cta.b64 P, [%0], %1;\n\t"
      "@!P bra W_%=;\n\t"
      "}" :: "r"(addr), "r"(parity) : "memory");
}
__device__ __forceinline__ void cluster_sync() {
  asm volatile("barrier.cluster.arrive.aligned;" ::: "memory");
  asm volatile("barrier.cluster.wait.aligned;" ::: "memory");
}
__device__ __forceinline__ u64 fma2(u64 a, u64 b, u64 c) {
  u64 d; asm("fma.rn.f32x2 %0, %1, %2, %3;" : "=l"(d) : "l"(a), "l"(b), "l"(c));
  return d;
}
__device__ __forceinline__ u64 mul2(u64 a, u64 b) {
  u64 d; asm("mul.rn.f32x2 %0, %1, %2;" : "=l"(d) : "l"(a), "l"(b));
  return d;
}
__device__ __forceinline__ u64 pack2(float lo, float hi) {
  u64 d; asm("mov.b64 %0, {%1, %2};" : "=l"(d) : "f"(lo), "f"(hi));
  return d;
}
__device__ __forceinline__ float2 unpack2(u64 v) {
  float2 r; asm("mov.b64 {%0, %1}, %2;" : "=f"(r.x), "=f"(r.y) : "l"(v));
  return r;
}
__device__ __forceinline__ float hsum(u64 v) {
  float2 a = unpack2(v);
  return a.x + a.y;
}
__device__ __forceinline__ void red4(float& a, float& b, float& c, float& d) {
#pragma unroll
  for (int off = 16; off; off >>= 1) {
    a += __shfl_xor_sync(0xffffffffu, a, off);
    b += __shfl_xor_sync(0xffffffffu, b, off);
    c += __shfl_xor_sync(0xffffffffu, c, off);
    d += __shfl_xor_sync(0xffffffffu, d, off);
  }
}
__device__ __forceinline__ float tanh_fast(float z) {
  float e = __expf(2.0f * z);
  return 1.0f - __fdividef(2.0f, e + 1.0f);
}

extern __shared__ float smem_dyn[];

__global__ void __launch_bounds__(NTHR, 1) __cluster_dims__(CLSZ, 1, 1)
stpn_kernel(
    const float* __restrict__ x,
    const float* __restrict__ W,
    const float* __restrict__ Lm,
    const float* __restrict__ Gm,
    const float* __restrict__ bias,
    const float* __restrict__ ow,
    const float* __restrict__ ob,
    float* __restrict__ out)
{
  float* sw = smem_dyn;
  float* sl = sw + kRows * kF;
  float* sg = sl + kRows * kF;
  __shared__ __align__(16) float sh[3][2][kH];   // h slots (DSMEM targets)
  __shared__ __align__(8) u64 smb[3];            // slot mbarriers

  const int tid  = threadIdx.x;
  const int lane = tid & 31;
  const int wid  = tid >> 5;
  const int gid  = blockIdx.x >> 3;   // cluster index
  const int rank = blockIdx.x & 7;    // rank within cluster
  const int bA   = gid * 2;
  const int bB   = bA + 1;
  const int grow0 = rank * kRows;
  const int lr0  = 2 * wid;
  const int row0 = grow0 + lr0;

  for (int i = tid; i < kRows * kF; i += NTHR) {
    const int r = i >> 9, c = i & 511;
    sw[i] = W[(grow0 + r) * kF + c];
    sl[i] = Lm[(grow0 + r) * kF + c];
    sg[i] = Gm[(grow0 + r) * kF + c];
  }
  if (tid == 0) {
    mbar_init(smem_u32(&smb[0]), 128);
    mbar_init(smem_u32(&smb[1]), 128);
    mbar_init(smem_u32(&smb[2]), 128);
  }
  const float bias0 = bias[row0];
  const float bias1 = bias[row0 + 1];
  __syncthreads();
  cluster_sync();   // mbarriers + weights visible before any remote traffic

  const uint32_t sh_base = smem_u32(&sh[0][0][0]);
  const uint32_t mb_base = smem_u32(&smb[0]);

  const u64* swp0 = (const u64*)(sw + lr0 * kF);
  const u64* swp1 = (const u64*)(sw + (lr0 + 1) * kF);
  const u64* slp0 = (const u64*)(sl + lr0 * kF);
  const u64* slp1 = (const u64*)(sl + (lr0 + 1) * kF);
  const u64* sgp0 = (const u64*)(sg + lr0 * kF);
  const u64* sgp1 = (const u64*)(sg + (lr0 + 1) * kF);

  // u = w + f (f=0)
  u64 uu[2][2][8];
#pragma unroll
  for (int q = 0; q < 8; ++q) {
    const int p = 64 * (q >> 1) + 2 * lane + (q & 1);
    const u64 w0 = swp0[p], w1 = swp1[p];
    uu[0][0][q] = w0; uu[0][1][q] = w0;
    uu[1][0][q] = w1; uu[1][1][q] = w1;
  }

  float iv[2][2];
  {
    u64 sp0 = mul2(uu[0][0][0], uu[0][0][0]);
    u64 sp1 = mul2(uu[1][0][0], uu[1][0][0]);
#pragma unroll
    for (int q = 1; q < 8; ++q) {
      sp0 = fma2(uu[0][0][q], uu[0][0][q], sp0);
      sp1 = fma2(uu[1][0][q], uu[1][0][q], sp1);
    }
    float s0 = hsum(sp0), s1 = hsum(sp1), s2 = 0.f, s3 = 0.f;
    red4(s0, s1, s2, s3);
    iv[0][0] = rsqrtf(s0); iv[0][1] = iv[0][0];
    iv[1][0] = rsqrtf(s1); iv[1][1] = iv[1][0];
  }

  float hn[2][2] = {{0.f, 0.f}, {0.f, 0.f}};

  for (int t = 0; t < kS; ++t) {
    const int wbs = t % 3;
    const int rbs = (t + 2) % 3;   // (t-1)%3 for t>0

    // ---- wait for h(t-1): local mbarrier (acquire, cluster scope) ----
    if (t > 0) {
      mbar_wait(mb_base + 8 * rbs, ((unsigned)(t - 1) / 3u) & 1u);
    }

    const u64* hpa = (const u64*)&sh[rbs][0][0];
    const u64* hpb = (const u64*)&sh[rbs][1][0];

    // ---- pre = ti . u ----
    {
      const u64* xpa = (const u64*)(x + ((size_t)bA * kS + t) * kI);
      const u64* xpb = (const u64*)(x + ((size_t)bB * kS + t) * kI);
      const u64 ta0 = xpa[2 * lane],      ta1 = xpa[2 * lane + 1];
      const u64 ta2 = xpa[64 + 2 * lane], ta3 = xpa[64 + 2 * lane + 1];
      const u64 tb0 = xpb[2 * lane],      tb1 = xpb[2 * lane + 1];
      const u64 tb2 = xpb[64 + 2 * lane], tb3 = xpb[64 + 2 * lane + 1];
      u64 ha0 = 0, ha1 = 0, ha2 = 0, ha3 = 0;
      u64 hb0 = 0, hb1 = 0, hb2 = 0, hb3 = 0;
      if (t > 0) {
        ha0 = hpa[2 * lane];      ha1 = hpa[2 * lane + 1];
        ha2 = hpa[64 + 2 * lane]; ha3 = hpa[64 + 2 * lane + 1];
        hb0 = hpb[2 * lane];      hb1 = hpb[2 * lane + 1];
        hb2 = hpb[64 + 2 * lane]; hb3 = hpb[64 + 2 * lane + 1];
      }
      u64 a00 = mul2(ta0, uu[0][0][0]);  u64 a10 = mul2(ta0, uu[1][0][0]);
      u64 a01 = mul2(tb0, uu[0][1][0]);  u64 a11 = mul2(tb0, uu[1][1][0]);
      a00 = fma2(ta1, uu[0][0][1], a00); a10 = fma2(ta1, uu[1][0][1], a10);
      a01 = fma2(tb1, uu[0][1][1], a01); a11 = fma2(tb1, uu[1][1][1], a11);
      a00 = fma2(ta2, uu[0][0][2], a00); a10 = fma2(ta2, uu[1][0][2], a10);
      a01 = fma2(tb2, uu[0][1][2], a01); a11 = fma2(tb2, uu[1][1][2], a11);
      a00 = fma2(ta3, uu[0][0][3], a00); a10 = fma2(ta3, uu[1][0][3], a10);
      a01 = fma2(tb3, uu[0][1][3], a01); a11 = fma2(tb3, uu[1][1][3], a11);
      a00 = fma2(ha0, uu[0][0][4], a00); a10 = fma2(ha0, uu[1][0][4], a10);
      a01 = fma2(hb0, uu[0][1][4], a01); a11 = fma2(hb0, uu[1][1][4], a11);
      a00 = fma2(ha1, uu[0][0][5], a00); a10 = fma2(ha1, uu[1][0][5], a10);
      a01 = fma2(hb1, uu[0][1][5], a01); a11 = fma2(hb1, uu[1][1][5], a11);
      a00 = fma2(ha2, uu[0][0][6], a00); a10 = fma2(ha2, uu[1][0][6], a10);
      a01 = fma2(hb2, uu[0][1][6], a01); a11 = fma2(hb2, uu[1][1][6], a11);
      a00 = fma2(ha3, uu[0][0][7], a00); a10 = fma2(ha3, uu[1][0][7], a10);
      a01 = fma2(hb3, uu[0][1][7], a01); a11 = fma2(hb3, uu[1][1][7], a11);
      float p00 = hsum(a00), p01 = hsum(a01);
      float p10 = hsum(a10), p11 = hsum(a11);
      red4(p00, p01, p10, p11);
      hn[0][0] = tanh_fast(fmaf(p00, iv[0][0], bias0));
      hn[0][1] = tanh_fast(fmaf(p01, iv[0][1], bias0));
      hn[1][0] = tanh_fast(fmaf(p10, iv[1][0], bias1));
      hn[1][1] = tanh_fast(fmaf(p11, iv[1][1], bias1));
    }

    // ---- publish h(t) to all 8 cluster CTAs (lanes 0..7, peer = lane) ----
    {
      const uint32_t aA = sh_base + (uint32_t)(((wbs * 2 + 0) * kH + row0) * 4);
      const uint32_t aB = sh_base + (uint32_t)(((wbs * 2 + 1) * kH + row0) * 4);
      if (lane < CLSZ) {
        const uint32_t rA = mapa_u32(aA, (uint32_t)lane);
        const uint32_t rB = mapa_u32(aB, (uint32_t)lane);
        st_cluster_u64(rA, pack2(hn[0][0], hn[1][0]));
        st_cluster_u64(rB, pack2(hn[0][1], hn[1][1]));
        const uint32_t rM = mapa_u32(mb_base + 8 * wbs, (uint32_t)lane);
        mbar_arrive_cluster(rM);   // release orders this thread's stores
      }
    }

    // ---- shadow: u' = w + (lam*iv)*(u-w) + (gam*hn)*ti ; sq ----
    {
      const u64 n1 = pack2(-1.0f, -1.0f);
      u64 ivp[2][2], ghp[2][2], sq[2][2];
#pragma unroll
      for (int r = 0; r < 2; ++r)
#pragma unroll
        for (int b = 0; b < 2; ++b) {
          ivp[r][b] = pack2(iv[r][b], iv[r][b]);
          ghp[r][b] = pack2(hn[r][b], hn[r][b]);
          sq[r][b]  = 0;
        }
      const u64* xpa = (const u64*)(x + ((size_t)bA * kS + t) * kI);
      const u64* xpb = (const u64*)(x + ((size_t)bB * kS + t) * kI);
#pragma unroll
      for (int k = 0; k < 4; ++k) {
        const int p = 64 * k + 2 * lane;
        const ulonglong2 w0p = *(const ulonglong2*)&swp0[p];
        const ulonglong2 w1p = *(const ulonglong2*)&swp1[p];
        const ulonglong2 l0p = *(const ulonglong2*)&slp0[p];
        const ulonglong2 l1p = *(const ulonglong2*)&slp1[p];
        const ulonglong2 g0p = *(const ulonglong2*)&sgp0[p];
        const ulonglong2 g1p = *(const ulonglong2*)&sgp1[p];
#pragma unroll
        for (int b = 0; b < 2; ++b) {
          u64 ti0, ti1;
          if (k < 2) {
            const u64* xp = b ? xpb : xpa;
            ti0 = xp[64 * k + 2 * lane];
            ti1 = xp[64 * k + 2 * lane + 1];
          } else if (t > 0) {
            const u64* hp = b ? hpb : hpa;
            ti0 = hp[64 * (k - 2) + 2 * lane];
            ti1 = hp[64 * (k - 2) + 2 * lane + 1];
          } else {
            ti0 = 0; ti1 = 0;
          }
#pragma unroll
          for (int r = 0; r < 2; ++r) {
            const u64 wA = r ? w1p.x : w0p.x, wB = r ? w1p.y : w0p.y;
            const u64 lA = r ? l1p.x : l0p.x, lB = r ? l1p.y : l0p.y;
            const u64 gA = r ? g1p.x : g0p.x, gB = r ? g1p.y : g0p.y;
            u64& Ua = uu[r][b][2 * k];
            u64& Ub = uu[r][b][2 * k + 1];
            {
              const u64 a = mul2(lA, ivp[r][b]);
              const u64 d = fma2(n1, wA, Ua);
              const u64 e = fma2(mul2(gA, ghp[r][b]), ti0, wA);
              Ua = fma2(a, d, e);
              sq[r][b] = fma2(Ua, Ua, sq[r][b]);
            }
            {
              const u64 a = mul2(lB, ivp[r][b]);
              const u64 d = fma2(n1, wB, Ub);
              const u64 e = fma2(mul2(gB, ghp[r][b]), ti1, wB);
              Ub = fma2(a, d, e);
              sq[r][b] = fma2(Ub, Ub, sq[r][b]);
            }
          }
        }
      }
      float s00 = hsum(sq[0][0]), s01 = hsum(sq[0][1]);
      float s10 = hsum(sq[1][0]), s11 = hsum(sq[1][1]);
      red4(s00, s01, s10, s11);
      iv[0][0] = rsqrtf(s00); iv[0][1] = rsqrtf(s01);
      iv[1][0] = rsqrtf(s10); iv[1][1] = rsqrtf(s11);
    }
  }

  // ---------------- epilogue ----------------
  {
    const u64 n1 = pack2(-1.0f, -1.0f);
    u64* fout = (u64*)(out + kB * kO + kB * kH);
#pragma unroll
    for (int r = 0; r < 2; ++r) {
      const u64* swr = r ? swp1 : swp0;
#pragma unroll
      for (int b = 0; b < 2; ++b) {
        const int bb = b ? bB : bA;
        u64* rowp = fout + (size_t)(bb * kH + row0 + r) * (kF / 2);
#pragma unroll
        for (int q = 0; q < 8; ++q) {
          const int p = 64 * (q >> 1) + 2 * lane + (q & 1);
          rowp[p] = fma2(n1, swr[p], uu[r][b][q]);
        }
      }
    }
  }
  if (lane == 0) {
    *(u64*)&out[kB * kO + bA * kH + row0] = pack2(hn[0][0], hn[1][0]);
    *(u64*)&out[kB * kO + bB * kH + row0] = pack2(hn[0][1], hn[1][1]);
  }

  // tag_space: ranks 0,1 use local sh slot of h(63)
  if (rank < 2) {
    mbar_wait(mb_base + 8 * ((kS - 1) % 3), ((kS - 1) / 3) & 1);
    const int bb = rank ? bB : bA;
    const float* hf = &sh[(kS - 1) % 3][rank][0];
#pragma unroll
    for (int j = 0; j < 8; ++j) {
      const int oo = wid * 8 + j;
      float p = 0.f;
#pragma unroll
      for (int mm = 0; mm < 8; ++mm) {
        p += hf[lane + 32 * mm] * ow[oo * kH + lane + 32 * mm];
      }
#pragma unroll
      for (int off = 16; off; off >>= 1) p += __shfl_xor_sync(0xffffffffu, p, off);
      if (lane == 0) out[bb * kO + oo] = p + ob[oo];
    }
  }

  cluster_sync();   // no CTA exits while peers may still touch its smem
}

extern "C" void kernel_launch(void* const* d_in, const int* in_sizes, int n_in,
                              void* d_out, int out_size) {
  (void)in_sizes; (void)n_in; (void)out_size;
  const int smem_bytes = 3 * kRows * kF * (int)sizeof(float);  // 196608
  cudaFuncSetAttribute(stpn_kernel,
                       cudaFuncAttributeMaxDynamicSharedMemorySize, smem_bytes);
  stpn_kernel<<<NCTA, NTHR, smem_bytes>>>(
      (const float*)d_in[0],
      (const float*)d_in[1],
      (const float*)d_in[2],
      (const float*)d_in[3],
      (const float*)d_in[4],
      (const float*)d_in[5],
      (const float*)d_in[6],
      (float*)d_out);
}

// round 13
// speedup vs baseline: 1.0674x; 1.0674x over previous
#include <cuda_runtime.h>

// Persistent STPN, R8 mechanics with 2 CTAs/SM for sync-latency overlap:
// 256 CTAs x 256 thr; CTA = 16 rows x 2 batches (warp = 2 rows x 2 batches,
// u = w + f in registers, 32 x u64). Group = 16 CTAs owning 2 batches;
// co-resident CTAs belong to different groups, so one computes while the
// other waits. Weights via LDS.128. Flag sync = R8's proven acquire/release.

#define NCTA 256
#define NTHR 256
#define GSZ 16

namespace {
constexpr int kB = 32;
constexpr int kS = 64;
constexpr int kI = 256;
constexpr int kH = 256;
constexpr int kO = 128;
constexpr int kF = 512;
constexpr int kRows = 16;   // h-rows per CTA
}

typedef unsigned long long u64;

__device__ unsigned g_flags[NCTA];      // monotonic steps completed per CTA
__device__ float g_hbuf[3][kB * kH];    // triple-buffered hidden state

__device__ __forceinline__ unsigned ld_acq(const unsigned* p) {
  unsigned v;
  asm volatile("ld.acquire.gpu.u32 %0, [%1];" : "=r"(v) : "l"(p) : "memory");
  return v;
}
__device__ __forceinline__ void st_rel(unsigned* p, unsigned v) {
  asm volatile("st.release.gpu.u32 [%0], %1;" :: "l"(p), "r"(v) : "memory");
}
__device__ __forceinline__ u64 fma2(u64 a, u64 b, u64 c) {
  u64 d; asm("fma.rn.f32x2 %0, %1, %2, %3;" : "=l"(d) : "l"(a), "l"(b), "l"(c));
  return d;
}
__device__ __forceinline__ u64 mul2(u64 a, u64 b) {
  u64 d; asm("mul.rn.f32x2 %0, %1, %2;" : "=l"(d) : "l"(a), "l"(b));
  return d;
}
__device__ __forceinline__ u64 pack2(float lo, float hi) {
  u64 d; asm("mov.b64 %0, {%1, %2};" : "=l"(d) : "f"(lo), "f"(hi));
  return d;
}
__device__ __forceinline__ float2 unpack2(u64 v) {
  float2 r; asm("mov.b64 {%0, %1}, %2;" : "=f"(r.x), "=f"(r.y) : "l"(v));
  return r;
}
__device__ __forceinline__ float hsum(u64 v) {
  float2 a = unpack2(v);
  return a.x + a.y;
}
__device__ __forceinline__ void red4(float& a, float& b, float& c, float& d) {
#pragma unroll
  for (int off = 16; off; off >>= 1) {
    a += __shfl_xor_sync(0xffffffffu, a, off);
    b += __shfl_xor_sync(0xffffffffu, b, off);
    c += __shfl_xor_sync(0xffffffffu, c, off);
    d += __shfl_xor_sync(0xffffffffu, d, off);
  }
}
__device__ __forceinline__ float tanh_fast(float z) {
  float e = __expf(2.0f * z);
  return 1.0f - __fdividef(2.0f, e + 1.0f);
}

extern __shared__ float smem_dyn[];  // sw | sl | sg : 16 rows x 512 each

__global__ void __launch_bounds__(NTHR, 2) stpn_kernel(
    const float* __restrict__ x,
    const float* __restrict__ W,
    const float* __restrict__ Lm,
    const float* __restrict__ Gm,
    const float* __restrict__ bias,
    const float* __restrict__ ow,
    const float* __restrict__ ob,
    float* __restrict__ out)
{
  float* sw = smem_dyn;
  float* sl = sw + kRows * kF;
  float* sg = sl + kRows * kF;
  __shared__ unsigned s_base;

  const int tid  = threadIdx.x;
  const int lane = tid & 31;
  const int wid  = tid >> 5;           // 0..7
  const int gid  = blockIdx.x >> 4;    // group 0..15
  const int rank = blockIdx.x & 15;    // 0..15 within group
  const int bA   = gid * 2;
  const int bB   = bA + 1;
  const int grow0 = rank * kRows;      // first global h-row of this CTA
  const int lr0  = 2 * wid;            // warp's first local row
  const int row0 = grow0 + lr0;

  for (int i = tid; i < kRows * kF; i += NTHR) {
    const int r = i >> 9, c = i & 511;
    sw[i] = W[(grow0 + r) * kF + c];
    sl[i] = Lm[(grow0 + r) * kF + c];
    sg[i] = Gm[(grow0 + r) * kF + c];
  }
  if (tid == 0) s_base = __ldcg(&g_flags[blockIdx.x]);
  const float bias0 = bias[row0];
  const float bias1 = bias[row0 + 1];
  __syncthreads();
  const unsigned base = s_base;

  const u64* swp0 = (const u64*)(sw + lr0 * kF);
  const u64* swp1 = (const u64*)(sw + (lr0 + 1) * kF);
  const u64* slp0 = (const u64*)(sl + lr0 * kF);
  const u64* slp1 = (const u64*)(sl + (lr0 + 1) * kF);
  const u64* sgp0 = (const u64*)(sg + lr0 * kF);
  const u64* sgp1 = (const u64*)(sg + (lr0 + 1) * kF);

  // u = w + f (f=0 initially)
  u64 uu[2][2][8];
#pragma unroll
  for (int q = 0; q < 8; ++q) {
    const int p = 64 * (q >> 1) + 2 * lane + (q & 1);
    const u64 w0 = swp0[p], w1 = swp1[p];
    uu[0][0][q] = w0; uu[0][1][q] = w0;
    uu[1][0][q] = w1; uu[1][1][q] = w1;
  }

  float iv[2][2];
  {
    u64 sp0 = mul2(uu[0][0][0], uu[0][0][0]);
    u64 sp1 = mul2(uu[1][0][0], uu[1][0][0]);
#pragma unroll
    for (int q = 1; q < 8; ++q) {
      sp0 = fma2(uu[0][0][q], uu[0][0][q], sp0);
      sp1 = fma2(uu[1][0][q], uu[1][0][q], sp1);
    }
    float s0 = hsum(sp0), s1 = hsum(sp1), s2 = 0.f, s3 = 0.f;
    red4(s0, s1, s2, s3);
    iv[0][0] = rsqrtf(s0); iv[0][1] = iv[0][0];
    iv[1][0] = rsqrtf(s1); iv[1][1] = iv[1][0];
  }

  float hn[2][2] = {{0.f, 0.f}, {0.f, 0.f}};
  int wb = 0, rb = 2;

  for (int t = 0; t < kS; ++t) {
    // ---- group wait: 16 flags (tids 0..15), then CTA barrier ----
    if (t > 0) {
      if (tid < GSZ) {
        const unsigned tg = base + (unsigned)t;
        const unsigned* fp = &g_flags[gid * GSZ + tid];
        while ((int)(ld_acq(fp) - tg) < 0) { }
      }
      __syncthreads();
    }

    // ---- pre[r][b] = ti[b] . u[r][b] ----
    {
      const u64* xpa = (const u64*)(x + ((size_t)bA * kS + t) * kI);
      const u64* xpb = (const u64*)(x + ((size_t)bB * kS + t) * kI);
      const u64* hpa = (const u64*)(&g_hbuf[rb][bA * kH]);
      const u64* hpb = (const u64*)(&g_hbuf[rb][bB * kH]);
      const u64 ta0 = xpa[2 * lane],      ta1 = xpa[2 * lane + 1];
      const u64 ta2 = xpa[64 + 2 * lane], ta3 = xpa[64 + 2 * lane + 1];
      const u64 tb0 = xpb[2 * lane],      tb1 = xpb[2 * lane + 1];
      const u64 tb2 = xpb[64 + 2 * lane], tb3 = xpb[64 + 2 * lane + 1];
      u64 ha0 = 0, ha1 = 0, ha2 = 0, ha3 = 0;
      u64 hb0 = 0, hb1 = 0, hb2 = 0, hb3 = 0;
      if (t > 0) {
        ha0 = __ldcg(hpa + 2 * lane);      ha1 = __ldcg(hpa + 2 * lane + 1);
        ha2 = __ldcg(hpa + 64 + 2 * lane); ha3 = __ldcg(hpa + 64 + 2 * lane + 1);
        hb0 = __ldcg(hpb + 2 * lane);      hb1 = __ldcg(hpb + 2 * lane + 1);
        hb2 = __ldcg(hpb + 64 + 2 * lane); hb3 = __ldcg(hpb + 64 + 2 * lane + 1);
      }
      u64 a00 = mul2(ta0, uu[0][0][0]);  u64 a10 = mul2(ta0, uu[1][0][0]);
      u64 a01 = mul2(tb0, uu[0][1][0]);  u64 a11 = mul2(tb0, uu[1][1][0]);
      a00 = fma2(ta1, uu[0][0][1], a00); a10 = fma2(ta1, uu[1][0][1], a10);
      a01 = fma2(tb1, uu[0][1][1], a01); a11 = fma2(tb1, uu[1][1][1], a11);
      a00 = fma2(ta2, uu[0][0][2], a00); a10 = fma2(ta2, uu[1][0][2], a10);
      a01 = fma2(tb2, uu[0][1][2], a01); a11 = fma2(tb2, uu[1][1][2], a11);
      a00 = fma2(ta3, uu[0][0][3], a00); a10 = fma2(ta3, uu[1][0][3], a10);
      a01 = fma2(tb3, uu[0][1][3], a01); a11 = fma2(tb3, uu[1][1][3], a11);
      a00 = fma2(ha0, uu[0][0][4], a00); a10 = fma2(ha0, uu[1][0][4], a10);
      a01 = fma2(hb0, uu[0][1][4], a01); a11 = fma2(hb0, uu[1][1][4], a11);
      a00 = fma2(ha1, uu[0][0][5], a00); a10 = fma2(ha1, uu[1][0][5], a10);
      a01 = fma2(hb1, uu[0][1][5], a01); a11 = fma2(hb1, uu[1][1][5], a11);
      a00 = fma2(ha2, uu[0][0][6], a00); a10 = fma2(ha2, uu[1][0][6], a10);
      a01 = fma2(hb2, uu[0][1][6], a01); a11 = fma2(hb2, uu[1][1][6], a11);
      a00 = fma2(ha3, uu[0][0][7], a00); a10 = fma2(ha3, uu[1][0][7], a10);
      a01 = fma2(hb3, uu[0][1][7], a01); a11 = fma2(hb3, uu[1][1][7], a11);
      float p00 = hsum(a00), p01 = hsum(a01);
      float p10 = hsum(a10), p11 = hsum(a11);
      red4(p00, p01, p10, p11);
      hn[0][0] = tanh_fast(fmaf(p00, iv[0][0], bias0));
      hn[0][1] = tanh_fast(fmaf(p01, iv[0][1], bias0));
      hn[1][0] = tanh_fast(fmaf(p10, iv[1][0], bias1));
      hn[1][1] = tanh_fast(fmaf(p11, iv[1][1], bias1));
    }

    if (lane == 0) {
      __stcg((u64*)&g_hbuf[wb][bA * kH + row0], pack2(hn[0][0], hn[1][0]));
      __stcg((u64*)&g_hbuf[wb][bB * kH + row0], pack2(hn[0][1], hn[1][1]));
    }
    __syncthreads();
    if (tid == 0) st_rel(&g_flags[blockIdx.x], base + (unsigned)(t + 1));

    // ---- shadow: u' = w + (lam*iv)*(u-w) + (gam*hn)*ti ; accumulate sq ----
    {
      const u64 n1 = pack2(-1.0f, -1.0f);
      u64 ivp[2][2], ghp[2][2], sq[2][2];
#pragma unroll
      for (int r = 0; r < 2; ++r)
#pragma unroll
        for (int b = 0; b < 2; ++b) {
          ivp[r][b] = pack2(iv[r][b], iv[r][b]);
          ghp[r][b] = pack2(hn[r][b], hn[r][b]);
          sq[r][b]  = 0;
        }
      const u64* xpa = (const u64*)(x + ((size_t)bA * kS + t) * kI);
      const u64* xpb = (const u64*)(x + ((size_t)bB * kS + t) * kI);
      const u64* hpa = (const u64*)(&g_hbuf[rb][bA * kH]);
      const u64* hpb = (const u64*)(&g_hbuf[rb][bB * kH]);
#pragma unroll
      for (int k = 0; k < 4; ++k) {
        const int p = 64 * k + 2 * lane;
        const ulonglong2 w0p = *(const ulonglong2*)&swp0[p];
        const ulonglong2 w1p = *(const ulonglong2*)&swp1[p];
        const ulonglong2 l0p = *(const ulonglong2*)&slp0[p];
        const ulonglong2 l1p = *(const ulonglong2*)&slp1[p];
        const ulonglong2 g0p = *(const ulonglong2*)&sgp0[p];
        const ulonglong2 g1p = *(const ulonglong2*)&sgp1[p];
#pragma unroll
        for (int b = 0; b < 2; ++b) {
          u64 ti0, ti1;
          if (k < 2) {
            const u64* xp = b ? xpb : xpa;
            ti0 = xp[64 * k + 2 * lane];
            ti1 = xp[64 * k + 2 * lane + 1];
          } else if (t > 0) {
            const u64* hp = b ? hpb : hpa;
            ti0 = __ldcg(hp + 64 * (k - 2) + 2 * lane);
            ti1 = __ldcg(hp + 64 * (k - 2) + 2 * lane + 1);
          } else {
            ti0 = 0; ti1 = 0;
          }
#pragma unroll
          for (int r = 0; r < 2; ++r) {
            const u64 wA = r ? w1p.x : w0p.x, wB = r ? w1p.y : w0p.y;
            const u64 lA = r ? l1p.x : l0p.x, lB = r ? l1p.y : l0p.y;
            const u64 gA = r ? g1p.x : g0p.x, gB = r ? g1p.y : g0p.y;
            u64& Ua = uu[r][b][2 * k];
            u64& Ub = uu[r][b][2 * k + 1];
            {
              const u64 a = mul2(lA, ivp[r][b]);
              const u64 d = fma2(n1, wA, Ua);
              const u64 e = fma2(mul2(gA, ghp[r][b]), ti0, wA);
              Ua = fma2(a, d, e);
              sq[r][b] = fma2(Ua, Ua, sq[r][b]);
            }
            {
              const u64 a = mul2(lB, ivp[r][b]);
              const u64 d = fma2(n1, wB, Ub);
              const u64 e = fma2(mul2(gB, ghp[r][b]), ti1, wB);
              Ub = fma2(a, d, e);
              sq[r][b] = fma2(Ub, Ub, sq[r][b]);
            }
          }
        }
      }
      float s00 = hsum(sq[0][0]), s01 = hsum(sq[0][1]);
      float s10 = hsum(sq[1][0]), s11 = hsum(sq[1][1]);
      red4(s00, s01, s10, s11);
      iv[0][0] = rsqrtf(s00); iv[0][1] = rsqrtf(s01);
      iv[1][0] = rsqrtf(s10); iv[1][1] = rsqrtf(s11);
    }

    rb = wb;
    wb = (wb == 2) ? 0 : wb + 1;
  }

  // ---------------- epilogue ----------------
  {
    const u64 n1 = pack2(-1.0f, -1.0f);
    u64* fout = (u64*)(out + kB * kO + kB * kH);
#pragma unroll
    for (int r = 0; r < 2; ++r) {
      const u64* swr = r ? swp1 : swp0;
#pragma unroll
      for (int b = 0; b < 2; ++b) {
        const int bb = b ? bB : bA;
        u64* rowp = fout + (size_t)(bb * kH + row0 + r) * (kF / 2);
#pragma unroll
        for (int q = 0; q < 8; ++q) {
          const int p = 64 * (q >> 1) + 2 * lane + (q & 1);
          rowp[p] = fma2(n1, swr[p], uu[r][b][q]);
        }
      }
    }
  }
  if (lane == 0) {
    *(u64*)&out[kB * kO + bA * kH + row0] = pack2(hn[0][0], hn[1][0]);
    *(u64*)&out[kB * kO + bB * kH + row0] = pack2(hn[0][1], hn[1][1]);
  }

  // tag_space: ranks 0,1 compute batches bA,bB after own group finishes
  if (rank < 2) {
    if (tid < GSZ) {
      const unsigned tg = base + (unsigned)kS;
      const unsigned* fp = &g_flags[gid * GSZ + tid];
      while ((int)(ld_acq(fp) - tg) < 0) { }
    }
    __syncthreads();
    const int bb = rank ? bB : bA;
    const float* hf = &g_hbuf[(kS - 1) % 3][bb * kH];
#pragma unroll
    for (int j = 0; j < 16; ++j) {
      const int oo = wid * 16 + j;
      float p = 0.f;
#pragma unroll
      for (int mm = 0; mm < 8; ++mm) {
        p += __ldcg(&hf[lane + 32 * mm]) * ow[oo * kH + lane + 32 * mm];
      }
#pragma unroll
      for (int off = 16; off; off >>= 1) p += __shfl_xor_sync(0xffffffffu, p, off);
      if (lane == 0) out[bb * kO + oo] = p + ob[oo];
    }
  }
}

extern "C" void kernel_launch(void* const* d_in, const int* in_sizes, int n_in,
                              void* d_out, int out_size) {
  (void)in_sizes; (void)n_in; (void)out_size;
  const int smem_bytes = 3 * kRows * kF * (int)sizeof(float);  // 98304
  cudaFuncSetAttribute(stpn_kernel,
                       cudaFuncAttributeMaxDynamicSharedMemorySize, smem_bytes);
  stpn_kernel<<<NCTA, NTHR, smem_bytes>>>(
      (const float*)d_in[0],
      (const float*)d_in[1],
      (const float*)d_in[2],
      (const float*)d_in[3],
      (const float*)d_in[4],
      (const float*)d_in[5],
      (const float*)d_in[6],
      (float*)d_out);
}

// round 14
// speedup vs baseline: 1.7330x; 1.6236x over previous
#include <cuda_runtime.h>

// Persistent STPN, R8 structure (16 groups x 8 CTAs, CTA = 32 rows x 2
// batches, warp = 2 rows x 2 batches, u = w + f in registers).
// R14: pre's h/x loads persist into the shadow (no redundant L2 reloads),
// iv/gh packed on-the-fly to free the registers, x(t+1) prefetched to L1.

#define NCTA 128
#define NTHR 512
#define GSZ 8

namespace {
constexpr int kB = 32;
constexpr int kS = 64;
constexpr int kI = 256;
constexpr int kH = 256;
constexpr int kO = 128;
constexpr int kF = 512;
constexpr int kRows = 32;
}

typedef unsigned long long u64;

__device__ unsigned g_flags[NCTA];
__device__ float g_hbuf[3][kB * kH];

__device__ __forceinline__ unsigned ld_acq(const unsigned* p) {
  unsigned v;
  asm volatile("ld.acquire.gpu.u32 %0, [%1];" : "=r"(v) : "l"(p) : "memory");
  return v;
}
__device__ __forceinline__ void st_rel(unsigned* p, unsigned v) {
  asm volatile("st.release.gpu.u32 [%0], %1;" :: "l"(p), "r"(v) : "memory");
}
__device__ __forceinline__ void prefetch_l1(const void* p) {
  asm volatile("prefetch.global.L1 [%0];" :: "l"(p));
}
__device__ __forceinline__ u64 fma2(u64 a, u64 b, u64 c) {
  u64 d; asm("fma.rn.f32x2 %0, %1, %2, %3;" : "=l"(d) : "l"(a), "l"(b), "l"(c));
  return d;
}
__device__ __forceinline__ u64 mul2(u64 a, u64 b) {
  u64 d; asm("mul.rn.f32x2 %0, %1, %2;" : "=l"(d) : "l"(a), "l"(b));
  return d;
}
__device__ __forceinline__ u64 pack2(float lo, float hi) {
  u64 d; asm("mov.b64 %0, {%1, %2};" : "=l"(d) : "f"(lo), "f"(hi));
  return d;
}
__device__ __forceinline__ float2 unpack2(u64 v) {
  float2 r; asm("mov.b64 {%0, %1}, %2;" : "=f"(r.x), "=f"(r.y) : "l"(v));
  return r;
}
__device__ __forceinline__ float hsum(u64 v) {
  float2 a = unpack2(v);
  return a.x + a.y;
}
__device__ __forceinline__ void red4(float& a, float& b, float& c, float& d) {
#pragma unroll
  for (int off = 16; off; off >>= 1) {
    a += __shfl_xor_sync(0xffffffffu, a, off);
    b += __shfl_xor_sync(0xffffffffu, b, off);
    c += __shfl_xor_sync(0xffffffffu, c, off);
    d += __shfl_xor_sync(0xffffffffu, d, off);
  }
}
__device__ __forceinline__ float tanh_fast(float z) {
  float e = __expf(2.0f * z);
  return 1.0f - __fdividef(2.0f, e + 1.0f);
}

extern __shared__ float smem_dyn[];

__global__ void __launch_bounds__(NTHR, 1) stpn_kernel(
    const float* __restrict__ x,
    const float* __restrict__ W,
    const float* __restrict__ Lm,
    const float* __restrict__ Gm,
    const float* __restrict__ bias,
    const float* __restrict__ ow,
    const float* __restrict__ ob,
    float* __restrict__ out)
{
  float* sw = smem_dyn;
  float* sl = sw + kRows * kF;
  float* sg = sl + kRows * kF;
  __shared__ unsigned s_base;

  const int tid  = threadIdx.x;
  const int lane = tid & 31;
  const int wid  = tid >> 5;
  const int gid  = blockIdx.x >> 3;
  const int rank = blockIdx.x & 7;
  const int bA   = gid * 2;
  const int bB   = bA + 1;
  const int grow0 = rank * kRows;
  const int lr0  = 2 * wid;
  const int row0 = grow0 + lr0;

  for (int i = tid; i < kRows * kF; i += NTHR) {
    const int r = i >> 9, c = i & 511;
    sw[i] = W[(grow0 + r) * kF + c];
    sl[i] = Lm[(grow0 + r) * kF + c];
    sg[i] = Gm[(grow0 + r) * kF + c];
  }
  if (tid == 0) s_base = __ldcg(&g_flags[blockIdx.x]);
  const float bias0 = bias[row0];
  const float bias1 = bias[row0 + 1];
  __syncthreads();
  const unsigned base = s_base;

  const u64* swp0 = (const u64*)(sw + lr0 * kF);
  const u64* swp1 = (const u64*)(sw + (lr0 + 1) * kF);
  const u64* slp0 = (const u64*)(sl + lr0 * kF);
  const u64* slp1 = (const u64*)(sl + (lr0 + 1) * kF);
  const u64* sgp0 = (const u64*)(sg + lr0 * kF);
  const u64* sgp1 = (const u64*)(sg + (lr0 + 1) * kF);

  // u = w + f (f=0 initially)
  u64 uu[2][2][8];
#pragma unroll
  for (int q = 0; q < 8; ++q) {
    const int p = 64 * (q >> 1) + 2 * lane + (q & 1);
    const u64 w0 = swp0[p], w1 = swp1[p];
    uu[0][0][q] = w0; uu[0][1][q] = w0;
    uu[1][0][q] = w1; uu[1][1][q] = w1;
  }

  float iv[2][2];
  {
    u64 sp0 = mul2(uu[0][0][0], uu[0][0][0]);
    u64 sp1 = mul2(uu[1][0][0], uu[1][0][0]);
#pragma unroll
    for (int q = 1; q < 8; ++q) {
      sp0 = fma2(uu[0][0][q], uu[0][0][q], sp0);
      sp1 = fma2(uu[1][0][q], uu[1][0][q], sp1);
    }
    float s0 = hsum(sp0), s1 = hsum(sp1), s2 = 0.f, s3 = 0.f;
    red4(s0, s1, s2, s3);
    iv[0][0] = rsqrtf(s0); iv[0][1] = iv[0][0];
    iv[1][0] = rsqrtf(s1); iv[1][1] = iv[1][0];
  }

  float hn[2][2] = {{0.f, 0.f}, {0.f, 0.f}};
  int wb = 0, rb = 2;

  for (int t = 0; t < kS; ++t) {
    // ---- group wait: 8 flags (tids 0..7), then CTA barrier ----
    if (t > 0) {
      if (tid < GSZ) {
        const unsigned tg = base + (unsigned)t;
        const unsigned* fp = &g_flags[gid * GSZ + tid];
        while ((int)(ld_acq(fp) - tg) < 0) { }
      }
      __syncthreads();
    }

    const u64* xpa = (const u64*)(x + ((size_t)bA * kS + t) * kI);
    const u64* xpb = (const u64*)(x + ((size_t)bB * kS + t) * kI);
    const u64* hpa = (const u64*)(&g_hbuf[rb][bA * kH]);
    const u64* hpb = (const u64*)(&g_hbuf[rb][bB * kH]);

    // ti registers persist from pre into shadow (h not reloaded).
    u64 ha0 = 0, ha1 = 0, ha2 = 0, ha3 = 0;
    u64 hb0 = 0, hb1 = 0, hb2 = 0, hb3 = 0;
    if (t > 0) {   // issue the long-latency h loads FIRST
      ha0 = __ldcg(hpa + 2 * lane);      ha1 = __ldcg(hpa + 2 * lane + 1);
      ha2 = __ldcg(hpa + 64 + 2 * lane); ha3 = __ldcg(hpa + 64 + 2 * lane + 1);
      hb0 = __ldcg(hpb + 2 * lane);      hb1 = __ldcg(hpb + 2 * lane + 1);
      hb2 = __ldcg(hpb + 64 + 2 * lane); hb3 = __ldcg(hpb + 64 + 2 * lane + 1);
    }
    const u64 ta0 = xpa[2 * lane],      ta1 = xpa[2 * lane + 1];
    const u64 ta2 = xpa[64 + 2 * lane], ta3 = xpa[64 + 2 * lane + 1];
    const u64 tb0 = xpb[2 * lane],      tb1 = xpb[2 * lane + 1];
    const u64 tb2 = xpb[64 + 2 * lane], tb3 = xpb[64 + 2 * lane + 1];

    // ---- pre = ti . u (x-part first: x is L1-resident via prefetch) ----
    {
      u64 a00 = mul2(ta0, uu[0][0][0]);  u64 a10 = mul2(ta0, uu[1][0][0]);
      u64 a01 = mul2(tb0, uu[0][1][0]);  u64 a11 = mul2(tb0, uu[1][1][0]);
      a00 = fma2(ta1, uu[0][0][1], a00); a10 = fma2(ta1, uu[1][0][1], a10);
      a01 = fma2(tb1, uu[0][1][1], a01); a11 = fma2(tb1, uu[1][1][1], a11);
      a00 = fma2(ta2, uu[0][0][2], a00); a10 = fma2(ta2, uu[1][0][2], a10);
      a01 = fma2(tb2, uu[0][1][2], a01); a11 = fma2(tb2, uu[1][1][2], a11);
      a00 = fma2(ta3, uu[0][0][3], a00); a10 = fma2(ta3, uu[1][0][3], a10);
      a01 = fma2(tb3, uu[0][1][3], a01); a11 = fma2(tb3, uu[1][1][3], a11);
      a00 = fma2(ha0, uu[0][0][4], a00); a10 = fma2(ha0, uu[1][0][4], a10);
      a01 = fma2(hb0, uu[0][1][4], a01); a11 = fma2(hb0, uu[1][1][4], a11);
      a00 = fma2(ha1, uu[0][0][5], a00); a10 = fma2(ha1, uu[1][0][5], a10);
      a01 = fma2(hb1, uu[0][1][5], a01); a11 = fma2(hb1, uu[1][1][5], a11);
      a00 = fma2(ha2, uu[0][0][6], a00); a10 = fma2(ha2, uu[1][0][6], a10);
      a01 = fma2(hb2, uu[0][1][6], a01); a11 = fma2(hb2, uu[1][1][6], a11);
      a00 = fma2(ha3, uu[0][0][7], a00); a10 = fma2(ha3, uu[1][0][7], a10);
      a01 = fma2(hb3, uu[0][1][7], a01); a11 = fma2(hb3, uu[1][1][7], a11);
      float p00 = hsum(a00), p01 = hsum(a01);
      float p10 = hsum(a10), p11 = hsum(a11);
      red4(p00, p01, p10, p11);
      hn[0][0] = tanh_fast(fmaf(p00, iv[0][0], bias0));
      hn[0][1] = tanh_fast(fmaf(p01, iv[0][1], bias0));
      hn[1][0] = tanh_fast(fmaf(p10, iv[1][0], bias1));
      hn[1][1] = tanh_fast(fmaf(p11, iv[1][1], bias1));
    }

    if (lane == 0) {
      __stcg((u64*)&g_hbuf[wb][bA * kH + row0], pack2(hn[0][0], hn[1][0]));
      __stcg((u64*)&g_hbuf[wb][bB * kH + row0], pack2(hn[0][1], hn[1][1]));
    }
    __syncthreads();
    if (tid == 0) st_rel(&g_flags[blockIdx.x], base + (unsigned)(t + 1));

    // ---- prefetch x(t+1) into L1 (warp 0; 16 x 128B lines) ----
    if (wid == 0 && t + 1 < kS) {
      if (lane < 8) {
        prefetch_l1(x + ((size_t)bA * kS + t + 1) * kI + lane * 32);
      } else if (lane < 16) {
        prefetch_l1(x + ((size_t)bB * kS + t + 1) * kI + (lane - 8) * 32);
      }
    }

    // ---- shadow: u' = w + (lam*iv)*(u-w) + (gam*hn)*ti ; accumulate sq ----
    {
      const u64 n1 = pack2(-1.0f, -1.0f);
      u64 sq[2][2] = {{0, 0}, {0, 0}};
#pragma unroll
      for (int k = 0; k < 4; ++k) {
        const int p = 64 * k + 2 * lane;
        const u64 w00 = swp0[p], w01 = swp0[p + 1];
        const u64 w10 = swp1[p], w11 = swp1[p + 1];
        const u64 l00 = slp0[p], l01 = slp0[p + 1];
        const u64 l10 = slp1[p], l11 = slp1[p + 1];
        const u64 g00 = sgp0[p], g01 = sgp0[p + 1];
        const u64 g10 = sgp1[p], g11 = sgp1[p + 1];
#pragma unroll
        for (int b = 0; b < 2; ++b) {
          u64 ti0, ti1;
          if (k == 0)      { ti0 = b ? tb0 : ta0; ti1 = b ? tb1 : ta1; }
          else if (k == 1) { ti0 = b ? tb2 : ta2; ti1 = b ? tb3 : ta3; }
          else if (k == 2) { ti0 = b ? hb0 : ha0; ti1 = b ? hb1 : ha1; }
          else             { ti0 = b ? hb2 : ha2; ti1 = b ? hb3 : ha3; }
#pragma unroll
          for (int r = 0; r < 2; ++r) {
            const u64 ivp = pack2(iv[r][b], iv[r][b]);
            const u64 ghp = pack2(hn[r][b], hn[r][b]);
            const u64 wA = r ? w10 : w00, wB = r ? w11 : w01;
            const u64 lA = r ? l10 : l00, lB = r ? l11 : l01;
            const u64 gA = r ? g10 : g00, gB = r ? g11 : g01;
            u64& Ua = uu[r][b][2 * k];
            u64& Ub = uu[r][b][2 * k + 1];
            {
              const u64 a = mul2(lA, ivp);
              const u64 d = fma2(n1, wA, Ua);
              const u64 e = fma2(mul2(gA, ghp), ti0, wA);
              Ua = fma2(a, d, e);
              sq[r][b] = fma2(Ua, Ua, sq[r][b]);
            }
            {
              const u64 a = mul2(lB, ivp);
              const u64 d = fma2(n1, wB, Ub);
              const u64 e = fma2(mul2(gB, ghp), ti1, wB);
              Ub = fma2(a, d, e);
              sq[r][b] = fma2(Ub, Ub, sq[r][b]);
            }
          }
        }
      }
      float s00 = hsum(sq[0][0]), s01 = hsum(sq[0][1]);
      float s10 = hsum(sq[1][0]), s11 = hsum(sq[1][1]);
      red4(s00, s01, s10, s11);
      iv[0][0] = rsqrtf(s00); iv[0][1] = rsqrtf(s01);
      iv[1][0] = rsqrtf(s10); iv[1][1] = rsqrtf(s11);
    }

    rb = wb;
    wb = (wb == 2) ? 0 : wb + 1;
  }

  // ---------------- epilogue ----------------
  {
    const u64 n1 = pack2(-1.0f, -1.0f);
    u64* fout = (u64*)(out + kB * kO + kB * kH);
#pragma unroll
    for (int r = 0; r < 2; ++r) {
      const u64* swr = r ? swp1 : swp0;
#pragma unroll
      for (int b = 0; b < 2; ++b) {
        const int bb = b ? bB : bA;
        u64* rowp = fout + (size_t)(bb * kH + row0 + r) * (kF / 2);
#pragma unroll
        for (int q = 0; q < 8; ++q) {
          const int p = 64 * (q >> 1) + 2 * lane + (q & 1);
          rowp[p] = fma2(n1, swr[p], uu[r][b][q]);
        }
      }
    }
  }
  if (lane == 0) {
    *(u64*)&out[kB * kO + bA * kH + row0] = pack2(hn[0][0], hn[1][0]);
    *(u64*)&out[kB * kO + bB * kH + row0] = pack2(hn[0][1], hn[1][1]);
  }

  // tag_space: ranks 0,1 compute batches bA,bB after own group finishes
  if (rank < 2) {
    if (tid < GSZ) {
      const unsigned tg = base + (unsigned)kS;
      const unsigned* fp = &g_flags[gid * GSZ + tid];
      while ((int)(ld_acq(fp) - tg) < 0) { }
    }
    __syncthreads();
    const int bb = rank ? bB : bA;
    const float* hf = &g_hbuf[(kS - 1) % 3][bb * kH];
#pragma unroll
    for (int j = 0; j < 8; ++j) {
      const int oo = wid * 8 + j;
      float p = 0.f;
#pragma unroll
      for (int mm = 0; mm < 8; ++mm) {
        p += __ldcg(&hf[lane + 32 * mm]) * ow[oo * kH + lane + 32 * mm];
      }
#pragma unroll
      for (int off = 16; off; off >>= 1) p += __shfl_xor_sync(0xffffffffu, p, off);
      if (lane == 0) out[bb * kO + oo] = p + ob[oo];
    }
  }
}

extern "C" void kernel_launch(void* const* d_in, const int* in_sizes, int n_in,
                              void* d_out, int out_size) {
  (void)in_sizes; (void)n_in; (void)out_size;
  const int smem_bytes = 3 * kRows * kF * (int)sizeof(float);  // 196608
  cudaFuncSetAttribute(stpn_kernel,
                       cudaFuncAttributeMaxDynamicSharedMemorySize, smem_bytes);
  stpn_kernel<<<NCTA, NTHR, smem_bytes>>>(
      (const float*)d_in[0],
      (const float*)d_in[1],
      (const float*)d_in[2],
      (const float*)d_in[3],
      (const float*)d_in[4],
      (const float*)d_in[5],
      (const float*)d_in[6],
      (float*)d_out);
}